// round 3
// baseline (speedup 1.0000x reference)
#include <cuda_runtime.h>
#include <cuda_bf16.h>
#include <math.h>

#define BB 128
#define LL 512
#define LAa 8
#define EE 300
#define HH 300
#define G3 900

__device__ __align__(16) int   g_mem_len[BB];
__device__ __align__(16) int   g_asp_len[BB];
__device__ __align__(16) int   g_left_len[BB];
__device__ __align__(16) int   g_right_len[BB];
__device__ __align__(16) float g_qdot[BB];
__device__ __align__(16) float g_attn_l[BB * LL];
__device__ __align__(16) float g_attn_r[BB * LL];
__device__ __align__(16) float g_xp_l[(size_t)BB * LL * G3];
__device__ __align__(16) float g_xp_r[(size_t)BB * LL * G3];
__device__ __align__(16) float g_memory[(size_t)BB * LL * EE];
__device__ __align__(16) float g_kx[(size_t)BB * LL * EE];
__device__ __align__(16) float g_vs[BB * EE];

__device__ __forceinline__ float sigf(float x) { return 1.0f / (1.0f + expf(-x)); }

// ---------------- K0: lengths, attn defaults, aspect mean -> qdot -------------
__global__ void k_init(const int* __restrict__ text, const int* __restrict__ aspi,
                       const int* __restrict__ xl, const int* __restrict__ xr,
                       const float* __restrict__ emb_aspect,
                       const float* __restrict__ w_q, const float* __restrict__ b_q,
                       const float* __restrict__ attn_w,
                       const float* __restrict__ mlp_l_b, const float* __restrict__ mlp_r_b)
{
    int b = blockIdx.x, tid = threadIdx.x;
    int ml = __syncthreads_count(text[b * LL + tid] != 0);
    int ll = __syncthreads_count(xl[b * LL + tid] != 0);
    int rl = __syncthreads_count(xr[b * LL + tid] != 0);
    int al = __syncthreads_count((tid < LAa) && (aspi[b * LAa + tid] != 0));
    if (tid == 0) { g_mem_len[b] = ml; g_left_len[b] = ll; g_right_len[b] = rl; g_asp_len[b] = al; }
    g_attn_l[b * LL + tid] = sigf(mlp_l_b[0]) + 0.5f;
    g_attn_r[b * LL + tid] = sigf(mlp_r_b[0]) + 0.5f;

    __shared__ float s_asp[EE];
    __shared__ float sred[16];
    if (tid < EE) {
        float acc = 0.f;
        #pragma unroll
        for (int a = 0; a < LAa; a++)
            if (a < al) acc += emb_aspect[(size_t)aspi[b * LAa + a] * EE + tid];
        s_asp[tid] = acc / (float)al;
    }
    __syncthreads();
    float val = 0.f;
    if (tid < EE) {
        float acc = b_q[tid];
        const float* wq = w_q + (size_t)tid * EE;
        for (int e = 0; e < EE; e++) acc += s_asp[e] * wq[e];
        val = acc * attn_w[EE + tid];
    }
    #pragma unroll
    for (int o = 16; o > 0; o >>= 1) val += __shfl_xor_sync(0xffffffffu, val, o);
    if ((tid & 31) == 0) sred[tid >> 5] = val;
    __syncthreads();
    if (tid == 0) {
        float s = 0.f;
        #pragma unroll
        for (int w = 0; w < 16; w++) s += sred[w];
        g_qdot[b] = s;
    }
}

// ---------------- K1: tiled fp32 GEMM, C[b,m,n] = Arow(b,m).W[n] + bias[n] ----
// Arow = emb[ids[b][m]] (ids != null)  else g_memory[b][m]
// dst_sel: 0 g_xp_l, 1 g_xp_r, 2 g_kx.  limit_sel: 0 none, 1 left, 2 right.
__global__ void __launch_bounds__(256) k_gemm(
    const float* __restrict__ Aext, const int* __restrict__ ids,
    const float* __restrict__ W, const float* __restrict__ bias,
    int N, int dst_sel, int limit_sel)
{
    const int K = EE;
    int b = blockIdx.z, m0 = blockIdx.y * 64, n0 = blockIdx.x * 64;
    int lim = (limit_sel == 1) ? g_left_len[b] : (limit_sel == 2) ? g_right_len[b] : LL;
    if (m0 >= lim) return;

    float* C = (dst_sel == 0) ? g_xp_l : (dst_sel == 1) ? g_xp_r : g_kx;
    float* Cb = C + (size_t)b * LL * N;
    const int* bids = ids ? (ids + (size_t)b * LL) : (const int*)0;

    __shared__ float As[16][64];
    __shared__ float Bs[16][64];

    int tid = threadIdx.x;
    int tx = tid & 15, ty = tid >> 4;
    int lrow = tid >> 2, lc4 = (tid & 3) << 2;

    int gm = m0 + lrow;
    const float* arow;
    if (bids) arow = Aext + (size_t)bids[gm] * K;
    else      arow = g_memory + ((size_t)b * LL + gm) * K;
    int gn = n0 + lrow;
    const float* brow = (gn < N) ? (W + (size_t)gn * K) : (const float*)0;

    float acc[4][4];
    #pragma unroll
    for (int i = 0; i < 4; i++)
        #pragma unroll
        for (int j = 0; j < 4; j++) acc[i][j] = 0.f;

    for (int k0 = 0; k0 < K; k0 += 16) {
        float4 av = make_float4(0.f, 0.f, 0.f, 0.f);
        float4 bv = make_float4(0.f, 0.f, 0.f, 0.f);
        if (k0 + lc4 < K) {
            av = *(const float4*)(arow + k0 + lc4);
            if (brow) bv = *(const float4*)(brow + k0 + lc4);
        }
        __syncthreads();
        As[lc4 + 0][lrow] = av.x; As[lc4 + 1][lrow] = av.y;
        As[lc4 + 2][lrow] = av.z; As[lc4 + 3][lrow] = av.w;
        Bs[lc4 + 0][lrow] = bv.x; Bs[lc4 + 1][lrow] = bv.y;
        Bs[lc4 + 2][lrow] = bv.z; Bs[lc4 + 3][lrow] = bv.w;
        __syncthreads();
        #pragma unroll
        for (int kk = 0; kk < 16; kk++) {
            float4 a  = *(const float4*)&As[kk][ty << 2];
            float4 bb = *(const float4*)&Bs[kk][tx << 2];
            acc[0][0] += a.x * bb.x; acc[0][1] += a.x * bb.y; acc[0][2] += a.x * bb.z; acc[0][3] += a.x * bb.w;
            acc[1][0] += a.y * bb.x; acc[1][1] += a.y * bb.y; acc[1][2] += a.y * bb.z; acc[1][3] += a.y * bb.w;
            acc[2][0] += a.z * bb.x; acc[2][1] += a.z * bb.y; acc[2][2] += a.z * bb.z; acc[2][3] += a.z * bb.w;
            acc[3][0] += a.w * bb.x; acc[3][1] += a.w * bb.y; acc[3][2] += a.w * bb.z; acc[3][3] += a.w * bb.w;
        }
    }
    #pragma unroll
    for (int i = 0; i < 4; i++) {
        int om = m0 + (ty << 2) + i;
        #pragma unroll
        for (int j = 0; j < 4; j++) {
            int on = n0 + (tx << 2) + j;
            if (on < N) Cb[(size_t)om * N + on] = acc[i][j] + bias[on];
        }
    }
}

// ---------------- K2: GRU recurrence, 2 sequences/block, 128 blocks ----------
// blocks 0..63: left seqs (2pb,2pb+1); blocks 64..127: right.
// thread j<300 owns hidden unit j. Emits attn[b][t] directly.
__global__ void __launch_bounds__(320) k_gru(
    const float* __restrict__ Whh_l, const float* __restrict__ bhh_l,
    const float* __restrict__ mlpw_l, const float* __restrict__ mlpb_l,
    const float* __restrict__ Whh_r, const float* __restrict__ bhh_r,
    const float* __restrict__ mlpw_r, const float* __restrict__ mlpb_r)
{
    int side = (blockIdx.x >= 64);
    int pb = side ? (blockIdx.x - 64) : blockIdx.x;
    const float* Whh  = side ? Whh_r  : Whh_l;
    const float* bhh  = side ? bhh_r  : bhh_l;
    const float* mlpw = side ? mlpw_r : mlpw_l;
    float mb          = side ? mlpb_r[0] : mlpb_l[0];
    const float* xp   = side ? g_xp_r : g_xp_l;
    const int* lens   = side ? g_right_len : g_left_len;
    float* attn       = side ? g_attn_r : g_attn_l;

    int s0 = pb * 2;
    int tid = threadIdx.x, lane = tid & 31, wid = tid >> 5, j = tid;

    __shared__ float sh[2][EE];
    __shared__ float parts[2][10];
    __shared__ int slen[2];

    int len0 = lens[s0], len1 = lens[s0 + 1];
    int tmax = max(len0, len1);
    if (tid < 2) slen[tid] = (tid == 0) ? len0 : len1;

    float wm = 0.f, bhr = 0.f, bhz = 0.f, bhn = 0.f;
    const float4 *Wr = 0, *Wz = 0, *Wn = 0;
    if (j < EE) {
        wm = mlpw[j];
        bhr = bhh[j]; bhz = bhh[HH + j]; bhn = bhh[2 * HH + j];
        Wr = (const float4*)(Whh + (size_t)j * HH);
        Wz = (const float4*)(Whh + (size_t)(j + HH) * HH);
        Wn = (const float4*)(Whh + (size_t)(j + 2 * HH) * HH);
        sh[0][j] = 0.f; sh[1][j] = 0.f;
    }
    const float* xp0 = xp + (size_t)(s0) * LL * G3;
    const float* xp1 = xp + (size_t)(s0 + 1) * LL * G3;
    __syncthreads();

    for (int t = 0; t < tmax; t++) {
        float ar0 = 0.f, az0 = 0.f, an0 = 0.f, ar1 = 0.f, az1 = 0.f, an1 = 0.f;
        if (j < EE) {
            const float4* h0 = (const float4*)sh[0];
            const float4* h1 = (const float4*)sh[1];
            #pragma unroll 5
            for (int kk = 0; kk < 75; kk++) {
                float4 wr = Wr[kk], wz = Wz[kk], wn = Wn[kk];
                float4 v0 = h0[kk], v1 = h1[kk];
                ar0 += wr.x * v0.x + wr.y * v0.y + wr.z * v0.z + wr.w * v0.w;
                az0 += wz.x * v0.x + wz.y * v0.y + wz.z * v0.z + wz.w * v0.w;
                an0 += wn.x * v0.x + wn.y * v0.y + wn.z * v0.z + wn.w * v0.w;
                ar1 += wr.x * v1.x + wr.y * v1.y + wr.z * v1.z + wr.w * v1.w;
                az1 += wz.x * v1.x + wz.y * v1.y + wz.z * v1.z + wz.w * v1.w;
                an1 += wn.x * v1.x + wn.y * v1.y + wn.z * v1.z + wn.w * v1.w;
            }
        }
        bool a0 = (t < len0), a1 = (t < len1);
        float hn0 = 0.f, hn1 = 0.f;
        if (j < EE) {
            if (a0) {
                float hold = sh[0][j];
                const float* g = xp0 + (size_t)t * G3;
                float r = sigf(g[j] + ar0 + bhr);
                float z = sigf(g[HH + j] + az0 + bhz);
                float n = tanhf(g[2 * HH + j] + r * (an0 + bhn));
                hn0 = (1.f - z) * n + z * hold;
            }
            if (a1) {
                float hold = sh[1][j];
                const float* g = xp1 + (size_t)t * G3;
                float r = sigf(g[j] + ar1 + bhr);
                float z = sigf(g[HH + j] + az1 + bhz);
                float n = tanhf(g[2 * HH + j] + r * (an1 + bhn));
                hn1 = (1.f - z) * n + z * hold;
            }
        }
        __syncthreads();
        if (j < EE) {
            if (a0) sh[0][j] = hn0;
            if (a1) sh[1][j] = hn1;
        }
        float v0 = (j < EE && a0) ? hn0 * wm : 0.f;
        float v1 = (j < EE && a1) ? hn1 * wm : 0.f;
        #pragma unroll
        for (int o = 16; o > 0; o >>= 1) {
            v0 += __shfl_xor_sync(0xffffffffu, v0, o);
            v1 += __shfl_xor_sync(0xffffffffu, v1, o);
        }
        if (lane == 0) { parts[0][wid] = v0; parts[1][wid] = v1; }
        __syncthreads();
        if (tid < 2 && t < slen[tid]) {
            float s = 0.f;
            #pragma unroll
            for (int w = 0; w < 10; w++) s += parts[tid][w];
            attn[(s0 + tid) * LL + t] = sigf(s + mb) + 0.5f;
        }
    }
}

// ---------------- K3: memory = emb[text] * scale ------------------------------
__global__ void k_mem(const int* __restrict__ text, const float* __restrict__ emb)
{
    int l = blockIdx.x, b = blockIdx.y, tid = threadIdx.x;
    if (tid >= EE) return;
    float* row = g_memory + ((size_t)b * LL + l) * EE;
    int ml = g_mem_len[b];
    if (l >= ml) { row[tid] = 0.f; return; }
    int astart = g_left_len[b] - g_asp_len[b];
    int aend = g_left_len[b];
    float al = g_attn_l[b * LL + l];
    int ridx = min(max(l - astart, 0), LL - 1);
    float arv = g_attn_r[b * LL + ridx];
    float sc = (l < astart) ? al : ((l < aend) ? (al + arv) : arv);
    int id = text[b * LL + l];
    row[tid] = emb[(size_t)id * EE + tid] * sc;
}

// ---------------- K4: v_s -----------------------------------------------------
__global__ void k_vs()
{
    int b = blockIdx.x, tid = threadIdx.x;
    if (tid >= EE) return;
    float acc = 0.f;
    const float* p = g_memory + (size_t)b * LL * EE + tid;
    for (int l = 0; l < LL; l++) acc += p[(size_t)l * EE];
    g_vs[b * EE + tid] = acc / (float)g_mem_len[b];
}

// ---------------- K5: score->softmax->v_ts->proj->mlp->dense ------------------
__global__ void __launch_bounds__(512) k_tail(
    const float* __restrict__ attn_w,
    const float* __restrict__ proj_w, const float* __restrict__ proj_b,
    const float* __restrict__ mlp_w, const float* __restrict__ mlp_b,
    const float* __restrict__ dense_w, const float* __restrict__ dense_b,
    float* __restrict__ out)
{
    int b = blockIdx.x, tid = threadIdx.x, lane = tid & 31, wid = tid >> 5;
    __shared__ float s_aw[EE];
    __shared__ float s_sc[LL];
    __shared__ float smax[16], ssum[16];
    __shared__ float s_v[EE], s_v2[EE];
    const float* kxb = g_kx + (size_t)b * LL * EE;
    if (tid < EE) s_aw[tid] = attn_w[tid];
    __syncthreads();
    float qd = g_qdot[b];
    for (int l = wid; l < LL; l += 16) {
        const float* row = kxb + (size_t)l * EE;
        float acc = 0.f;
        for (int e = lane; e < EE; e += 32) acc += row[e] * s_aw[e];
        #pragma unroll
        for (int o = 16; o > 0; o >>= 1) acc += __shfl_xor_sync(0xffffffffu, acc, o);
        if (lane == 0) s_sc[l] = tanhf(acc + qd);
    }
    __syncthreads();
    float x = s_sc[tid];
    float m = x;
    #pragma unroll
    for (int o = 16; o > 0; o >>= 1) m = fmaxf(m, __shfl_xor_sync(0xffffffffu, m, o));
    if (lane == 0) smax[wid] = m;
    __syncthreads();
    float bm = smax[0];
    #pragma unroll
    for (int w = 1; w < 16; w++) bm = fmaxf(bm, smax[w]);
    float p = expf(x - bm);
    float sm = p;
    #pragma unroll
    for (int o = 16; o > 0; o >>= 1) sm += __shfl_xor_sync(0xffffffffu, sm, o);
    if (lane == 0) ssum[wid] = sm;
    __syncthreads();
    float tot = 0.f;
    #pragma unroll
    for (int w = 0; w < 16; w++) tot += ssum[w];
    s_sc[tid] = p / tot;
    __syncthreads();
    // v_ts (pre-proj) in s_v
    if (tid < EE) {
        float acc = 0.f;
        for (int l = 0; l < LL; l++) acc += s_sc[l] * kxb[(size_t)l * EE + tid];
        s_v[tid] = acc;
    }
    __syncthreads();
    // proj + v_s -> s_v2
    if (tid < EE) {
        float acc = proj_b[tid];
        const float* w = proj_w + (size_t)tid * EE;
        for (int e = 0; e < EE; e++) acc += s_v[e] * w[e];
        s_v2[tid] = acc + g_vs[b * EE + tid];
    }
    __syncthreads();
    // mlp tanh -> s_v
    if (tid < EE) {
        float acc = mlp_b[tid];
        const float* w = mlp_w + (size_t)tid * EE;
        for (int e = 0; e < EE; e++) acc += s_v2[e] * w[e];
        s_v[tid] = tanhf(acc);
    }
    __syncthreads();
    // dense: 3 outputs, one warp each
    if (wid < 3) {
        const float* w = dense_w + (size_t)wid * EE;
        float acc = 0.f;
        for (int e = lane; e < EE; e += 32) acc += s_v[e] * w[e];
        #pragma unroll
        for (int o = 16; o > 0; o >>= 1) acc += __shfl_xor_sync(0xffffffffu, acc, o);
        if (lane == 0) out[b * 3 + wid] = acc + dense_b[wid];
    }
}

extern "C" void kernel_launch(void* const* d_in, const int* in_sizes, int n_in,
                              void* d_out, int out_size)
{
    const int*   text  = (const int*)d_in[0];
    const int*   aspi  = (const int*)d_in[1];
    const int*   xl    = (const int*)d_in[2];
    const int*   xr    = (const int*)d_in[3];
    const float* emb   = (const float*)d_in[4];
    const float* emb_a = (const float*)d_in[5];
    const float* Wih_l = (const float*)d_in[6];
    const float* Whh_l = (const float*)d_in[7];
    const float* bih_l = (const float*)d_in[8];
    const float* bhh_l = (const float*)d_in[9];
    const float* Wih_r = (const float*)d_in[10];
    const float* Whh_r = (const float*)d_in[11];
    const float* bih_r = (const float*)d_in[12];
    const float* bhh_r = (const float*)d_in[13];
    const float* mlw_l = (const float*)d_in[14];
    const float* mlb_l = (const float*)d_in[15];
    const float* mlw_r = (const float*)d_in[16];
    const float* mlb_r = (const float*)d_in[17];
    const float* w_k   = (const float*)d_in[18];
    const float* b_k   = (const float*)d_in[19];
    const float* w_q   = (const float*)d_in[20];
    const float* b_q   = (const float*)d_in[21];
    const float* aw    = (const float*)d_in[22];
    const float* pw    = (const float*)d_in[23];
    const float* pb    = (const float*)d_in[24];
    const float* mw    = (const float*)d_in[25];
    const float* mb    = (const float*)d_in[26];
    const float* dw    = (const float*)d_in[27];
    const float* db    = (const float*)d_in[28];
    float* out = (float*)d_out;

    k_init<<<BB, 512>>>(text, aspi, xl, xr, emb_a, w_q, b_q, aw, mlb_l, mlb_r);

    dim3 gx((G3 + 63) / 64, LL / 64, BB);
    k_gemm<<<gx, 256>>>(emb, xl, Wih_l, bih_l, G3, 0, 1);
    k_gemm<<<gx, 256>>>(emb, xr, Wih_r, bih_r, G3, 1, 2);

    k_gru<<<BB, 320>>>(Whh_l, bhh_l, mlw_l, mlb_l, Whh_r, bhh_r, mlw_r, mlb_r);

    k_mem<<<dim3(LL, BB), 320>>>(text, emb);
    k_vs<<<BB, 320>>>();

    dim3 gk((EE + 63) / 64, LL / 64, BB);
    k_gemm<<<gk, 256>>>(emb, (const int*)0, w_k, b_k, EE, 2, 0);

    k_tail<<<BB, 512>>>(aw, pw, pb, mw, mb, dw, db, out);
}